// round 2
// baseline (speedup 1.0000x reference)
#include <cuda_runtime.h>

#define BATCH 128
#define DG 512
#define DH 1024
#define LAM 0.95f
#define ETA 0.5f
#define LN_EPS 1e-5f
#define NTHR 512
#define NWARP 16

// ---------------------------------------------------------------------------
// Block-level LayerNorm + ReLU over DH=1024 values in smem.
// Each thread owns elements t and t+512. Trailing sync protects s_red reuse.
// ---------------------------------------------------------------------------
__device__ __forceinline__ void block_ln_relu(
    const float* __restrict__ src, float* __restrict__ dst,
    float* __restrict__ red, int t, int w, int lane,
    float g0, float g1, float be0, float be1)
{
    float x0 = src[t];
    float x1 = src[t + NTHR];
    float s  = x0 + x1;
    float ss = fmaf(x0, x0, x1 * x1);
    #pragma unroll
    for (int o = 16; o > 0; o >>= 1) {
        s  += __shfl_xor_sync(0xffffffffu, s,  o);
        ss += __shfl_xor_sync(0xffffffffu, ss, o);
    }
    if (lane == 0) { red[w] = s; red[NWARP + w] = ss; }
    __syncthreads();
    if (t < 32) {
        float a = (lane < NWARP) ? red[lane] : 0.f;
        float c = (lane < NWARP) ? red[NWARP + lane] : 0.f;
        #pragma unroll
        for (int o = 8; o > 0; o >>= 1) {
            a += __shfl_xor_sync(0xffffffffu, a, o);
            c += __shfl_xor_sync(0xffffffffu, c, o);
        }
        if (lane == 0) { red[0] = a; red[1] = c; }
    }
    __syncthreads();
    const float mu   = red[0] * (1.0f / DH);
    const float var  = red[1] * (1.0f / DH) - mu * mu;
    const float rstd = rsqrtf(var + LN_EPS);
    dst[t]        = fmaxf(0.f, (x0 - mu) * rstd * g0 + be0);
    dst[t + NTHR] = fmaxf(0.f, (x1 - mu) * rstd * g1 + be1);
    __syncthreads();
}

// ---------------------------------------------------------------------------
// One block per batch. Everything fused:
//   base = Wh@hp + Wg@z + bh          (W from L2 after first touch)
//   h = relu(LN(base))
//   3x: y = base + A[b]@h ; h = relu(LN(y))     (A streamed from HBM, __ldcs)
//   A_k[b] = LAM*A[b] + ETA*h h^T ; outH[b] = h (streamed, __stcs)
// ---------------------------------------------------------------------------
__global__ __launch_bounds__(NTHR, 1)
void fused_rnnfw_kernel(const float* __restrict__ z,
                        const float* __restrict__ h_prev,
                        const float* __restrict__ A,
                        const float* __restrict__ Wh,
                        const float* __restrict__ Wg,
                        const float* __restrict__ bh,
                        const float* __restrict__ gamma,
                        const float* __restrict__ beta,
                        float* __restrict__ outH,
                        float* __restrict__ outA)
{
    __shared__ float s_hz[DH + DG];   // h_prev[b] ++ z[b]
    __shared__ float s_base[DH];
    __shared__ float s_y[DH];
    __shared__ float s_h[DH];
    __shared__ float s_red[2 * NWARP];

    const int b    = blockIdx.x;
    const int t    = threadIdx.x;
    const int w    = t >> 5;
    const int lane = t & 31;

    // per-thread LN params for elements t and t+512
    const float g0  = gamma[t],  g1  = gamma[t + NTHR];
    const float be0 = beta[t],   be1 = beta[t + NTHR];

    // ---- load h_prev[b] and z[b] into smem ----
    if (t < 256)
        reinterpret_cast<float4*>(s_hz)[t] =
            reinterpret_cast<const float4*>(h_prev + b * DH)[t];
    else if (t < 384)
        reinterpret_cast<float4*>(s_hz + DH)[t - 256] =
            reinterpret_cast<const float4*>(z + b * DG)[t - 256];
    __syncthreads();

    // ---- base = Wh @ hp + Wg @ z + bh (warp-per-row, 2 rows interleaved) ----
    {
        const float4* hp4 = reinterpret_cast<const float4*>(s_hz);
        const float4* z4  = reinterpret_cast<const float4*>(s_hz + DH);
        for (int rr = 0; rr < 64; rr += 2) {
            const int r0 = w * 64 + rr;
            const float4* W0 = reinterpret_cast<const float4*>(Wh + (size_t)r0 * DH);
            const float4* W1 = W0 + 256;
            const float4* G0 = reinterpret_cast<const float4*>(Wg + (size_t)r0 * DG);
            const float4* G1 = G0 + 128;
            float a0 = 0.f, a1 = 0.f;
            #pragma unroll
            for (int it = 0; it < 8; it++) {
                float4 w0 = W0[lane + it * 32];
                float4 w1 = W1[lane + it * 32];
                float4 hv = hp4[lane + it * 32];
                a0 += w0.x * hv.x + w0.y * hv.y + w0.z * hv.z + w0.w * hv.w;
                a1 += w1.x * hv.x + w1.y * hv.y + w1.z * hv.z + w1.w * hv.w;
            }
            #pragma unroll
            for (int it = 0; it < 4; it++) {
                float4 w0 = G0[lane + it * 32];
                float4 w1 = G1[lane + it * 32];
                float4 zv = z4[lane + it * 32];
                a0 += w0.x * zv.x + w0.y * zv.y + w0.z * zv.z + w0.w * zv.w;
                a1 += w1.x * zv.x + w1.y * zv.y + w1.z * zv.z + w1.w * zv.w;
            }
            #pragma unroll
            for (int o = 16; o > 0; o >>= 1) {
                a0 += __shfl_xor_sync(0xffffffffu, a0, o);
                a1 += __shfl_xor_sync(0xffffffffu, a1, o);
            }
            if (lane == 0) {
                s_base[r0]     = a0 + bh[r0];
                s_base[r0 + 1] = a1 + bh[r0 + 1];
            }
        }
    }
    __syncthreads();

    // ---- h = relu(LN(base)) ----
    block_ln_relu(s_base, s_h, s_red, t, w, lane, g0, g1, be0, be1);

    // ---- inner fast-weight loop: 3 x (y = base + A@h ; h = relu(LN(y))) ----
    const float4* __restrict__ Ab =
        reinterpret_cast<const float4*>(A + (size_t)b * DH * DH);
    const float4* h4 = reinterpret_cast<const float4*>(s_h);

    for (int step = 0; step < 3; step++) {
        for (int rr = 0; rr < 64; rr += 2) {
            const int r0 = w * 64 + rr;
            const float4* Ar0 = Ab + (size_t)r0 * 256;
            const float4* Ar1 = Ar0 + 256;
            float a0 = 0.f, a1 = 0.f;
            #pragma unroll
            for (int it = 0; it < 8; it++) {
                float4 v0 = __ldcs(Ar0 + lane + it * 32);
                float4 v1 = __ldcs(Ar1 + lane + it * 32);
                float4 hv = h4[lane + it * 32];
                a0 += v0.x * hv.x + v0.y * hv.y + v0.z * hv.z + v0.w * hv.w;
                a1 += v1.x * hv.x + v1.y * hv.y + v1.z * hv.z + v1.w * hv.w;
            }
            #pragma unroll
            for (int o = 16; o > 0; o >>= 1) {
                a0 += __shfl_xor_sync(0xffffffffu, a0, o);
                a1 += __shfl_xor_sync(0xffffffffu, a1, o);
            }
            if (lane == 0) {
                s_y[r0]     = s_base[r0]     + a0;
                s_y[r0 + 1] = s_base[r0 + 1] + a1;
            }
        }
        __syncthreads();
        block_ln_relu(s_y, s_h, s_red, t, w, lane, g0, g1, be0, be1);
    }

    // ---- emit h_t ----
    if (t < 256)
        reinterpret_cast<float4*>(outH + b * DH)[t] = h4[t];

    // ---- A_k = LAM*A + ETA*h h^T (streamed) ----
    {
        const int  col = t & 255;     // float4 column
        const int  rh  = t >> 8;      // row parity (0/1)
        const float4 hv = h4[col];
        float4* __restrict__ Ob =
            reinterpret_cast<float4*>(outA + (size_t)b * DH * DH);

        #pragma unroll 8
        for (int r = rh; r < DH; r += 2) {
            const float hi = s_h[r] * ETA;
            float4 a = __ldcs(Ab + (size_t)r * 256 + col);
            float4 o;
            o.x = fmaf(LAM, a.x, hi * hv.x);
            o.y = fmaf(LAM, a.y, hi * hv.y);
            o.z = fmaf(LAM, a.z, hi * hv.z);
            o.w = fmaf(LAM, a.w, hi * hv.w);
            __stcs(Ob + (size_t)r * 256 + col, o);
        }
    }
}

// ---------------------------------------------------------------------------
extern "C" void kernel_launch(void* const* d_in, const int* in_sizes, int n_in,
                              void* d_out, int out_size)
{
    const float* z      = (const float*)d_in[0];
    const float* h_prev = (const float*)d_in[1];
    const float* A_prev = (const float*)d_in[2];
    const float* W_h    = (const float*)d_in[3];
    const float* W_g    = (const float*)d_in[4];
    const float* b_h    = (const float*)d_in[5];
    const float* gamma  = (const float*)d_in[6];
    const float* beta   = (const float*)d_in[7];

    float* outH = (float*)d_out;                 // h_t: 128*1024
    float* outA = (float*)d_out + BATCH * DH;    // A_k: 128*1024*1024

    fused_rnnfw_kernel<<<BATCH, NTHR>>>(z, h_prev, A_prev, W_h, W_g, b_h,
                                        gamma, beta, outH, outA);
}

// round 3
// speedup vs baseline: 1.1682x; 1.1682x over previous
#include <cuda_runtime.h>

#define BATCH 128
#define DG 512
#define DH 1024
#define LAM 0.95f
#define ETA 0.5f
#define LN_EPS 1e-5f

// Scratch (allocation-free): base pre-activation and ping-pong matvec results.
__device__ float g_base[BATCH * DH];
__device__ float g_y0[BATCH * DH];
__device__ float g_y1[BATCH * DH];

// ---------------------------------------------------------------------------
// Kernel 1: base[b][n] = sum_k h_prev[b][k]*W_h[n][k] + sum_k z[b][k]*W_g[n][k] + b_h[n]
// Tiled 32x32x32 GEMM over concatenated K = 1024 (W_h) + 512 (W_g).
// ---------------------------------------------------------------------------
__global__ void base_gemm_kernel(const float* __restrict__ Hp,
                                 const float* __restrict__ Z,
                                 const float* __restrict__ Wh,
                                 const float* __restrict__ Wg,
                                 const float* __restrict__ bh)
{
    __shared__ float Hs[32][33];
    __shared__ float Ws[32][33];

    const int tid = threadIdx.x;
    const int tx = tid & 15;
    const int ty = tid >> 4;
    const int bm0 = blockIdx.x * 32;
    const int n0  = blockIdx.y * 32;

    float acc00 = 0.f, acc01 = 0.f, acc10 = 0.f, acc11 = 0.f;

    for (int k0 = 0; k0 < DH + DG; k0 += 32) {
        const float* src;
        const float* wsrc;
        int K, kk0;
        if (k0 < DH) { src = Hp; wsrc = Wh; K = DH; kk0 = k0; }
        else         { src = Z;  wsrc = Wg; K = DG; kk0 = k0 - DH; }

        #pragma unroll
        for (int l = 0; l < 4; l++) {
            int idx = tid + l * 256;
            int r = idx >> 5, c = idx & 31;
            Hs[r][c] = src[(bm0 + r) * K + kk0 + c];
            Ws[r][c] = wsrc[(n0 + r) * K + kk0 + c];
        }
        __syncthreads();

        #pragma unroll
        for (int kk = 0; kk < 32; kk++) {
            float h0 = Hs[ty * 2][kk];
            float h1 = Hs[ty * 2 + 1][kk];
            float w0 = Ws[tx * 2][kk];
            float w1 = Ws[tx * 2 + 1][kk];
            acc00 += h0 * w0; acc01 += h0 * w1;
            acc10 += h1 * w0; acc11 += h1 * w1;
        }
        __syncthreads();
    }

    const int r0 = bm0 + ty * 2;
    const int c0 = n0 + tx * 2;
    const float bias0 = bh[c0];
    const float bias1 = bh[c0 + 1];
    g_base[r0 * DH + c0]           = acc00 + bias0;
    g_base[r0 * DH + c0 + 1]       = acc01 + bias1;
    g_base[(r0 + 1) * DH + c0]     = acc10 + bias0;
    g_base[(r0 + 1) * DH + c0 + 1] = acc11 + bias1;
}

// ---------------------------------------------------------------------------
// In-block LN+ReLU: 256 threads compute h[b] (1024 floats) into s_h.
// Reads base[b] (+ optional y[b]) from L2. Trailing __syncthreads included.
// ---------------------------------------------------------------------------
__device__ __forceinline__ void compute_h(const float* __restrict__ base_b,
                                          const float* __restrict__ y_b,
                                          const float* __restrict__ gamma,
                                          const float* __restrict__ beta,
                                          float* __restrict__ s_h,
                                          float* __restrict__ s_red,
                                          int t)
{
    const int w = t >> 5, lane = t & 31;

    float4 x = reinterpret_cast<const float4*>(base_b)[t];
    if (y_b) {
        float4 y = reinterpret_cast<const float4*>(y_b)[t];
        x.x += y.x; x.y += y.y; x.z += y.z; x.w += y.w;
    }
    float s  = (x.x + x.y) + (x.z + x.w);
    float ss = fmaf(x.x, x.x, x.y * x.y) + fmaf(x.z, x.z, x.w * x.w);

    #pragma unroll
    for (int o = 16; o > 0; o >>= 1) {
        s  += __shfl_xor_sync(0xffffffffu, s,  o);
        ss += __shfl_xor_sync(0xffffffffu, ss, o);
    }
    if (lane == 0) { s_red[w] = s; s_red[8 + w] = ss; }
    __syncthreads();
    if (t < 32) {
        float a = (lane < 8) ? s_red[lane]     : 0.f;
        float c = (lane < 8) ? s_red[8 + lane] : 0.f;
        #pragma unroll
        for (int o = 4; o > 0; o >>= 1) {
            a += __shfl_xor_sync(0xffffffffu, a, o);
            c += __shfl_xor_sync(0xffffffffu, c, o);
        }
        if (lane == 0) { s_red[0] = a; s_red[1] = c; }
    }
    __syncthreads();

    const float mu   = s_red[0] * (1.0f / DH);
    const float var  = s_red[1] * (1.0f / DH) - mu * mu;
    const float rstd = rsqrtf(var + LN_EPS);

    float4 g  = reinterpret_cast<const float4*>(gamma)[t];
    float4 be = reinterpret_cast<const float4*>(beta)[t];
    float4 h;
    h.x = fmaxf(0.f, (x.x - mu) * rstd * g.x + be.x);
    h.y = fmaxf(0.f, (x.y - mu) * rstd * g.y + be.y);
    h.z = fmaxf(0.f, (x.z - mu) * rstd * g.z + be.z);
    h.w = fmaxf(0.f, (x.w - mu) * rstd * g.w + be.w);
    reinterpret_cast<float4*>(s_h)[t] = h;
    __syncthreads();
}

// ---------------------------------------------------------------------------
// Kernel 2 (x3): h = relu(LN(base [+ yin])) computed in-block, then
// yout[b][rows] = A[b][rows] @ h.  grid = (16 chunks, 128 batches), 256 thr.
// ---------------------------------------------------------------------------
__global__ __launch_bounds__(256)
void matvec_ln_kernel(const float* __restrict__ A,
                      const float* __restrict__ yin,    // may be null
                      float* __restrict__ yout,
                      const float* __restrict__ gamma,
                      const float* __restrict__ beta)
{
    __shared__ float s_h[DH];
    __shared__ float s_red[16];

    const int b = blockIdx.y;
    const int chunk = blockIdx.x;
    const int t = threadIdx.x;
    const int w = t >> 5, lane = t & 31;

    compute_h(g_base + b * DH, yin ? yin + b * DH : nullptr,
              gamma, beta, s_h, s_red, t);

    const float4* __restrict__ Ab =
        reinterpret_cast<const float4*>(A + (size_t)b * DH * DH);
    const float4* h4 = reinterpret_cast<const float4*>(s_h);

    #pragma unroll
    for (int rr = 0; rr < 8; rr += 2) {
        const int r0 = chunk * 64 + w * 8 + rr;
        const float4* Ar0 = Ab + (size_t)r0 * 256;
        const float4* Ar1 = Ar0 + 256;

        float a00 = 0.f, a01 = 0.f, a10 = 0.f, a11 = 0.f;
        #pragma unroll
        for (int it = 0; it < 8; it += 2) {
            float4 v00 = __ldcs(Ar0 + lane + (it + 0) * 32);
            float4 v01 = __ldcs(Ar0 + lane + (it + 1) * 32);
            float4 v10 = __ldcs(Ar1 + lane + (it + 0) * 32);
            float4 v11 = __ldcs(Ar1 + lane + (it + 1) * 32);
            float4 h0  = h4[lane + (it + 0) * 32];
            float4 h1  = h4[lane + (it + 1) * 32];
            a00 += v00.x * h0.x + v00.y * h0.y + v00.z * h0.z + v00.w * h0.w;
            a01 += v01.x * h1.x + v01.y * h1.y + v01.z * h1.z + v01.w * h1.w;
            a10 += v10.x * h0.x + v10.y * h0.y + v10.z * h0.z + v10.w * h0.w;
            a11 += v11.x * h1.x + v11.y * h1.y + v11.z * h1.z + v11.w * h1.w;
        }
        float acc0 = a00 + a01;
        float acc1 = a10 + a11;
        #pragma unroll
        for (int o = 16; o > 0; o >>= 1) {
            acc0 += __shfl_xor_sync(0xffffffffu, acc0, o);
            acc1 += __shfl_xor_sync(0xffffffffu, acc1, o);
        }
        if (lane == 0) {
            yout[b * DH + r0]     = acc0;
            yout[b * DH + r0 + 1] = acc1;
        }
    }
}

// ---------------------------------------------------------------------------
// Kernel 3: h3 = relu(LN(base + yin)) in-block, then
// A_k = LAM*A + ETA*h3 h3^T streamed; chunk 0 also emits h_t.
// grid = (64 chunks of 16 rows, 128 batches), 256 thr.
// ---------------------------------------------------------------------------
__global__ __launch_bounds__(256)
void update_ln_kernel(const float* __restrict__ A,
                      const float* __restrict__ yin,
                      const float* __restrict__ gamma,
                      const float* __restrict__ beta,
                      float* __restrict__ outH,
                      float* __restrict__ outA)
{
    __shared__ float s_h[DH];
    __shared__ float s_red[16];

    const int b = blockIdx.y;
    const int chunk = blockIdx.x;
    const int t = threadIdx.x;

    compute_h(g_base + b * DH, yin + b * DH, gamma, beta, s_h, s_red, t);

    const float4* h4 = reinterpret_cast<const float4*>(s_h);
    if (chunk == 0)
        reinterpret_cast<float4*>(outH + b * DH)[t] = h4[t];

    const float4* __restrict__ Ab =
        reinterpret_cast<const float4*>(A + (size_t)b * DH * DH);
    float4* __restrict__ Ob =
        reinterpret_cast<float4*>(outA + (size_t)b * DH * DH);

    const float4 hv = h4[t];

    #pragma unroll
    for (int r = 0; r < 16; r++) {
        const int row = chunk * 16 + r;
        const float hi = s_h[row] * ETA;
        float4 a = __ldcs(Ab + (size_t)row * 256 + t);
        float4 o;
        o.x = fmaf(LAM, a.x, hi * hv.x);
        o.y = fmaf(LAM, a.y, hi * hv.y);
        o.z = fmaf(LAM, a.z, hi * hv.z);
        o.w = fmaf(LAM, a.w, hi * hv.w);
        __stcs(Ob + (size_t)row * 256 + t, o);
    }
}

// ---------------------------------------------------------------------------
extern "C" void kernel_launch(void* const* d_in, const int* in_sizes, int n_in,
                              void* d_out, int out_size)
{
    const float* z      = (const float*)d_in[0];
    const float* h_prev = (const float*)d_in[1];
    const float* A_prev = (const float*)d_in[2];
    const float* W_h    = (const float*)d_in[3];
    const float* W_g    = (const float*)d_in[4];
    const float* b_h    = (const float*)d_in[5];
    const float* gamma  = (const float*)d_in[6];
    const float* beta   = (const float*)d_in[7];

    float* outH = (float*)d_out;                 // h_t: 128*1024
    float* outA = (float*)d_out + BATCH * DH;    // A_k: 128*1024*1024

    float* y0;  cudaGetSymbolAddress((void**)&y0, g_y0);
    float* y1;  cudaGetSymbolAddress((void**)&y1, g_y1);

    base_gemm_kernel<<<dim3(BATCH / 32, DH / 32), 256>>>(h_prev, z, W_h, W_g, b_h);

    matvec_ln_kernel<<<dim3(16, BATCH), 256>>>(A_prev, nullptr, y0, gamma, beta);
    matvec_ln_kernel<<<dim3(16, BATCH), 256>>>(A_prev, y0,      y1, gamma, beta);
    matvec_ln_kernel<<<dim3(16, BATCH), 256>>>(A_prev, y1,      y0, gamma, beta);

    update_ln_kernel<<<dim3(64, BATCH), 256>>>(A_prev, y0, gamma, beta, outH, outA);
}